// round 1
// baseline (speedup 1.0000x reference)
#include <cuda_runtime.h>
#include <math_constants.h>

#define BATCH 16
#define SEQ   577
#define DM    768
#define NH    12
#define DKH   64
#define NP    576   // SEQ - 1 (patch tokens)

// ---------------- scratch (allocation-free per harness rules) ----------------
__device__ float g_Q[BATCH * SEQ * DM];    // Q projection, later reused for FC output
__device__ float g_K[BATCH * SEQ * DM];
__device__ float g_V[BATCH * SEQ * DM];
__device__ float g_att[BATCH * SEQ * DM];  // attention output (head-merged)
__device__ float g_pen[(size_t)BATCH * NP * NP];
__device__ float g_rn[BATCH * NP];

// ---------------- generic fp32 GEMM: C[M,768] = A[M,768] @ W[768,768] --------
// 64x64 tile, 16x16 threads, 4x4 per thread, k-depth 8.
__global__ void sgemm_768(const float* __restrict__ A, const float* __restrict__ W,
                          float* __restrict__ C, int M) {
    __shared__ float As[8][64];
    __shared__ float Ws[8][64];
    const int tx = threadIdx.x, ty = threadIdx.y;
    const int tid = ty * 16 + tx;
    const int row0 = blockIdx.y * 64;
    const int col0 = blockIdx.x * 64;
    float acc[4][4] = {};

    for (int k0 = 0; k0 < 768; k0 += 8) {
        #pragma unroll
        for (int t = tid; t < 512; t += 256) {
            int r = t >> 3, kk = t & 7;
            int gr = row0 + r;
            As[kk][r] = (gr < M) ? A[(size_t)gr * 768 + k0 + kk] : 0.f;
        }
        #pragma unroll
        for (int t = tid; t < 512; t += 256) {
            int kk = t >> 6, c = t & 63;
            Ws[kk][c] = W[(size_t)(k0 + kk) * 768 + col0 + c];
        }
        __syncthreads();
        #pragma unroll
        for (int kk = 0; kk < 8; kk++) {
            float4 a4 = *(const float4*)&As[kk][ty * 4];
            float4 w4 = *(const float4*)&Ws[kk][tx * 4];
            float av[4] = {a4.x, a4.y, a4.z, a4.w};
            float wv[4] = {w4.x, w4.y, w4.z, w4.w};
            #pragma unroll
            for (int i = 0; i < 4; i++)
                #pragma unroll
                for (int j = 0; j < 4; j++)
                    acc[i][j] = fmaf(av[i], wv[j], acc[i][j]);
        }
        __syncthreads();
    }
    #pragma unroll
    for (int i = 0; i < 4; i++) {
        int gr = row0 + ty * 4 + i;
        if (gr < M) {
            #pragma unroll
            for (int j = 0; j < 4; j++)
                C[(size_t)gr * 768 + col0 + tx * 4 + j] = acc[i][j];
        }
    }
}

// ---------------- embedding row inverse-norms --------------------------------
__global__ void rnorm_kernel(const float* __restrict__ emb) {
    int b = blockIdx.y, i = blockIdx.x;
    const float* row = emb + (size_t)(b * SEQ + 1 + i) * DM;
    float s = 0.f;
    for (int c = threadIdx.x; c < DM; c += 256) { float v = row[c]; s += v * v; }
    __shared__ float red[8];
    #pragma unroll
    for (int o = 16; o; o >>= 1) s += __shfl_xor_sync(0xffffffffu, s, o);
    if ((threadIdx.x & 31) == 0) red[threadIdx.x >> 5] = s;
    __syncthreads();
    if (threadIdx.x < 8) {
        float v = red[threadIdx.x];
        #pragma unroll
        for (int o = 4; o; o >>= 1) v += __shfl_xor_sync(0xffu, v, o);
        if (threadIdx.x == 0) g_rn[b * NP + i] = rsqrtf(v + 1e-12f);
    }
}

// ---------------- penalty[b,i,j] = cos_sim(e_i,e_j) * dist(p_i,p_j) ----------
// sim GEMM per batch (576x576x768) + geometric epilogue.
__global__ void penalty_kernel(const float* __restrict__ emb, const float* __restrict__ pos) {
    int b = blockIdx.z;
    int i0 = blockIdx.y * 32, j0 = blockIdx.x * 32;
    __shared__ float Ei[32][33];
    __shared__ float Ej[32][33];
    const int tx = threadIdx.x, ty = threadIdx.y;
    const int tid = ty * 16 + tx;
    float a00 = 0.f, a01 = 0.f, a10 = 0.f, a11 = 0.f;

    for (int k0 = 0; k0 < DM; k0 += 32) {
        for (int t = tid; t < 1024; t += 256) {
            int r = t >> 5, kk = t & 31;
            Ei[r][kk] = emb[(size_t)(b * SEQ + 1 + i0 + r) * DM + k0 + kk];
            Ej[r][kk] = emb[(size_t)(b * SEQ + 1 + j0 + r) * DM + k0 + kk];
        }
        __syncthreads();
        #pragma unroll 8
        for (int kk = 0; kk < 32; kk++) {
            float x0 = Ei[ty * 2][kk], x1 = Ei[ty * 2 + 1][kk];
            float y0 = Ej[tx * 2][kk], y1 = Ej[tx * 2 + 1][kk];
            a00 = fmaf(x0, y0, a00); a01 = fmaf(x0, y1, a01);
            a10 = fmaf(x1, y0, a10); a11 = fmaf(x1, y1, a11);
        }
        __syncthreads();
    }
    float accs[2][2] = {{a00, a01}, {a10, a11}};
    #pragma unroll
    for (int ii = 0; ii < 2; ii++) {
        int gi = i0 + ty * 2 + ii;
        float pix = pos[((size_t)b * NP + gi) * 2 + 0];
        float piy = pos[((size_t)b * NP + gi) * 2 + 1];
        float rni = g_rn[b * NP + gi];
        #pragma unroll
        for (int jj = 0; jj < 2; jj++) {
            int gj = j0 + tx * 2 + jj;
            float dx = pix - pos[((size_t)b * NP + gj) * 2 + 0];
            float dy = piy - pos[((size_t)b * NP + gj) * 2 + 1];
            float dist = sqrtf(dx * dx + dy * dy + 1e-12f);
            g_pen[((size_t)b * NP + gi) * NP + gj] = accs[ii][jj] * rni * g_rn[b * NP + gj] * dist;
        }
    }
}

// ---------------- flash-style attention with penalty bias --------------------
// BM=64 query rows, BN=32 key cols/tile, 256 threads: thread = (row r, quad q),
// each owns 8 logit cols and 16 output dims.
__global__ void attn_kernel() {
    const int BM = 64, BN = 32;
    __shared__ float Qs[BM][68];
    __shared__ float Ks[BN][68];
    __shared__ float Vs[BN][68];
    __shared__ float Ps[BM][BN + 1];

    const int b = blockIdx.z, h = blockIdx.y, i0 = blockIdx.x * BM;
    const int tid = threadIdx.x;
    const int r = tid >> 2, q = tid & 3;

    for (int t = tid; t < BM * 64; t += 256) {
        int rr = t >> 6, d = t & 63;
        int gi = i0 + rr;
        Qs[rr][d] = (gi < SEQ) ? g_Q[(size_t)(b * SEQ + gi) * DM + h * DKH + d] : 0.f;
    }

    float O[16] = {};
    float m = -CUDART_INF_F, l = 0.f;
    const int gi = i0 + r;

    const int NT = (SEQ + BN - 1) / BN;  // 19
    for (int jt = 0; jt < NT; jt++) {
        const int j0 = jt * BN;
        __syncthreads();  // previous-iter Vs/Ps reads done (also orders Q load at jt=0)
        for (int t = tid; t < BN * 64; t += 256) {
            int cc = t >> 6, d = t & 63;
            int gj = j0 + cc;
            float kv = 0.f, vv = 0.f;
            if (gj < SEQ) {
                kv = g_K[(size_t)(b * SEQ + gj) * DM + h * DKH + d];
                vv = g_V[(size_t)(b * SEQ + gj) * DM + h * DKH + d];
            }
            Ks[cc][d] = kv;
            Vs[cc][d] = vv;
        }
        __syncthreads();

        float s[8] = {};
        #pragma unroll
        for (int k = 0; k < 64; k += 4) {
            float4 qv = *(const float4*)&Qs[r][k];
            #pragma unroll
            for (int cc = 0; cc < 8; cc++) {
                float4 kv = *(const float4*)&Ks[q * 8 + cc][k];
                s[cc] += qv.x * kv.x + qv.y * kv.y + qv.z * kv.z + qv.w * kv.w;
            }
        }

        float mloc = -CUDART_INF_F;
        #pragma unroll
        for (int cc = 0; cc < 8; cc++) {
            int gj = j0 + q * 8 + cc;
            float val = s[cc] * 0.125f;  // 1 / sqrt(64)
            if (gi >= 1 && gi < SEQ && gj >= 1 && gj < SEQ)
                val -= g_pen[((size_t)b * NP + gi - 1) * NP + (gj - 1)];
            if (gj >= SEQ) val = -CUDART_INF_F;
            s[cc] = val;
            mloc = fmaxf(mloc, val);
        }
        mloc = fmaxf(mloc, __shfl_xor_sync(0xffffffffu, mloc, 1));
        mloc = fmaxf(mloc, __shfl_xor_sync(0xffffffffu, mloc, 2));
        float mnew = fmaxf(m, mloc);
        float scale = __expf(m - mnew);

        float ssum = 0.f;
        #pragma unroll
        for (int cc = 0; cc < 8; cc++) {
            float e = __expf(s[cc] - mnew);
            Ps[r][q * 8 + cc] = e;
            ssum += e;
        }
        ssum += __shfl_xor_sync(0xffffffffu, ssum, 1);
        ssum += __shfl_xor_sync(0xffffffffu, ssum, 2);
        l = l * scale + ssum;
        m = mnew;
        #pragma unroll
        for (int dd = 0; dd < 16; dd++) O[dd] *= scale;
        __syncthreads();  // Ps complete (cross-quad), Vs ready

        #pragma unroll 4
        for (int c = 0; c < BN; c++) {
            float p = Ps[r][c];
            #pragma unroll
            for (int d4 = 0; d4 < 4; d4++) {
                float4 vv = *(const float4*)&Vs[c][q * 16 + d4 * 4];
                O[d4 * 4 + 0] = fmaf(p, vv.x, O[d4 * 4 + 0]);
                O[d4 * 4 + 1] = fmaf(p, vv.y, O[d4 * 4 + 1]);
                O[d4 * 4 + 2] = fmaf(p, vv.z, O[d4 * 4 + 2]);
                O[d4 * 4 + 3] = fmaf(p, vv.w, O[d4 * 4 + 3]);
            }
        }
    }

    if (gi < SEQ) {
        float inv = 1.f / l;
        #pragma unroll
        for (int dd = 0; dd < 16; dd++)
            g_att[(size_t)(b * SEQ + gi) * DM + h * DKH + q * 16 + dd] = O[dd] * inv;
    }
}

// ---------------- residual add + LayerNorm -----------------------------------
__global__ void ln_kernel(const float* __restrict__ fc, const float* __restrict__ resid,
                          const float* __restrict__ gamma, const float* __restrict__ beta,
                          float* __restrict__ out) {
    const int row = blockIdx.x;
    const float* f = fc + (size_t)row * DM;
    const float* rsd = resid + (size_t)row * DM;
    float x[3], s = 0.f, s2 = 0.f;
    #pragma unroll
    for (int t = 0; t < 3; t++) {
        int c = threadIdx.x + t * 256;
        float v = f[c] + rsd[c];
        x[t] = v; s += v; s2 += v * v;
    }
    __shared__ float r1[8], r2[8];
    #pragma unroll
    for (int o = 16; o; o >>= 1) {
        s  += __shfl_xor_sync(0xffffffffu, s, o);
        s2 += __shfl_xor_sync(0xffffffffu, s2, o);
    }
    if ((threadIdx.x & 31) == 0) { r1[threadIdx.x >> 5] = s; r2[threadIdx.x >> 5] = s2; }
    __syncthreads();
    __shared__ float smu, srstd;
    if (threadIdx.x < 8) {
        float a = r1[threadIdx.x], bsum = r2[threadIdx.x];
        #pragma unroll
        for (int o = 4; o; o >>= 1) {
            a    += __shfl_xor_sync(0xffu, a, o);
            bsum += __shfl_xor_sync(0xffu, bsum, o);
        }
        if (threadIdx.x == 0) {
            float mu = a * (1.f / DM);
            float var = bsum * (1.f / DM) - mu * mu;
            smu = mu;
            srstd = rsqrtf(var + 1e-6f);
        }
    }
    __syncthreads();
    float mu = smu, rstd = srstd;
    #pragma unroll
    for (int t = 0; t < 3; t++) {
        int c = threadIdx.x + t * 256;
        out[(size_t)row * DM + c] = (x[t] - mu) * rstd * gamma[c] + beta[c];
    }
}

// ---------------- launch ------------------------------------------------------
extern "C" void kernel_launch(void* const* d_in, const int* in_sizes, int n_in,
                              void* d_out, int out_size) {
    const float* q     = (const float*)d_in[0];
    const float* k     = (const float*)d_in[1];
    const float* v     = (const float*)d_in[2];
    const float* pos   = (const float*)d_in[3];
    const float* emb   = (const float*)d_in[4];
    const float* w_qs  = (const float*)d_in[5];
    const float* w_ks  = (const float*)d_in[6];
    const float* w_vs  = (const float*)d_in[7];
    const float* w_fc  = (const float*)d_in[8];
    const float* gamma = (const float*)d_in[9];
    const float* beta  = (const float*)d_in[10];
    float* out = (float*)d_out;

    float *Qp, *Kp, *Vp, *att;
    cudaGetSymbolAddress((void**)&Qp,  g_Q);
    cudaGetSymbolAddress((void**)&Kp,  g_K);
    cudaGetSymbolAddress((void**)&Vp,  g_V);
    cudaGetSymbolAddress((void**)&att, g_att);

    const int M = BATCH * SEQ;  // 9232
    dim3 gb(12, (M + 63) / 64);
    dim3 tb(16, 16);
    sgemm_768<<<gb, tb>>>(q, w_qs, Qp, M);
    sgemm_768<<<gb, tb>>>(k, w_ks, Kp, M);
    sgemm_768<<<gb, tb>>>(v, w_vs, Vp, M);

    rnorm_kernel<<<dim3(NP, BATCH), 256>>>(emb);
    penalty_kernel<<<dim3(NP / 32, NP / 32, BATCH), dim3(16, 16)>>>(emb, pos);

    attn_kernel<<<dim3((SEQ + 63) / 64, NH, BATCH), 256>>>();

    sgemm_768<<<gb, tb>>>(att, w_fc, Qp, M);  // reuse g_Q for FC output
    ln_kernel<<<M, 256>>>(Qp, q, gamma, beta, out);
}

// round 2
// speedup vs baseline: 1.3820x; 1.3820x over previous
#include <cuda_runtime.h>
#include <math_constants.h>

#define BATCH 16
#define SEQ   577
#define DM    768
#define NH    12
#define DKH   64
#define NP    576   // SEQ - 1 (patch tokens)

// ---------------- scratch (allocation-free per harness rules) ----------------
__device__ float g_Q[BATCH * SEQ * DM];    // Q projection, later reused for FC output
__device__ float g_K[BATCH * SEQ * DM];
__device__ float g_V[BATCH * SEQ * DM];
__device__ float g_att[BATCH * SEQ * DM];  // attention output (head-merged)
__device__ float g_pen[(size_t)BATCH * NP * NP];
__device__ float g_En[(size_t)BATCH * NP * DM];  // normalized embeddings (tf32)

__device__ __forceinline__ unsigned f2tf(float x) {
    unsigned u;
    asm("cvt.rna.tf32.f32 %0, %1;" : "=r"(u) : "f"(x));
    return u;
}
__device__ __forceinline__ float f2tff(float x) { return __uint_as_float(f2tf(x)); }

__device__ __forceinline__ void mma_tf32(float* d, const unsigned* a, const unsigned* b) {
    asm volatile(
        "mma.sync.aligned.m16n8k8.row.col.f32.tf32.tf32.f32 "
        "{%0,%1,%2,%3},{%4,%5,%6,%7},{%8,%9},{%0,%1,%2,%3};"
        : "+f"(d[0]), "+f"(d[1]), "+f"(d[2]), "+f"(d[3])
        : "r"(a[0]), "r"(a[1]), "r"(a[2]), "r"(a[3]), "r"(b[0]), "r"(b[1]));
}

// ---------------- tf32 tensor-core GEMM: C[M,768] = A[M,768] @ W[768,768] -----
// Block 128x128x32, 256 threads = 8 warps (2m x 4n), warp tile 64x32.
__global__ __launch_bounds__(256, 2)
void tgemm_768(const float* __restrict__ A, const float* __restrict__ W,
               float* __restrict__ C, int M) {
    __shared__ float As[128][36];
    __shared__ float Bs[32][132];
    const int tid = threadIdx.x;
    const int wid = tid >> 5, lane = tid & 31;
    const int g = lane >> 2, t4 = lane & 3;
    const int wm = (wid >> 2) * 64, wn = (wid & 3) * 32;
    const int row0 = blockIdx.y * 128, col0 = blockIdx.x * 128;

    float acc[4][4][4] = {};
    const int arow = tid >> 1, acol = (tid & 1) * 16;
    const int brow = tid >> 3, bcol = (tid & 7) * 16;

    for (int k0 = 0; k0 < 768; k0 += 32) {
        const int gr = row0 + arow;
        #pragma unroll
        for (int i = 0; i < 4; i++) {
            float4 v = (gr < M) ? *(const float4*)&A[(size_t)gr * 768 + k0 + acol + i * 4]
                                : make_float4(0.f, 0.f, 0.f, 0.f);
            v.x = f2tff(v.x); v.y = f2tff(v.y); v.z = f2tff(v.z); v.w = f2tff(v.w);
            *(float4*)&As[arow][acol + i * 4] = v;
        }
        #pragma unroll
        for (int i = 0; i < 4; i++) {
            float4 v = *(const float4*)&W[(size_t)(k0 + brow) * 768 + col0 + bcol + i * 4];
            v.x = f2tff(v.x); v.y = f2tff(v.y); v.z = f2tff(v.z); v.w = f2tff(v.w);
            *(float4*)&Bs[brow][bcol + i * 4] = v;
        }
        __syncthreads();

        #pragma unroll
        for (int kk = 0; kk < 32; kk += 8) {
            unsigned af[4][4], bf[4][2];
            #pragma unroll
            for (int mt = 0; mt < 4; mt++) {
                int r = wm + mt * 16;
                af[mt][0] = __float_as_uint(As[r + g][kk + t4]);
                af[mt][1] = __float_as_uint(As[r + g + 8][kk + t4]);
                af[mt][2] = __float_as_uint(As[r + g][kk + t4 + 4]);
                af[mt][3] = __float_as_uint(As[r + g + 8][kk + t4 + 4]);
            }
            #pragma unroll
            for (int nt = 0; nt < 4; nt++) {
                int c = wn + nt * 8;
                bf[nt][0] = __float_as_uint(Bs[kk + t4][c + g]);
                bf[nt][1] = __float_as_uint(Bs[kk + t4 + 4][c + g]);
            }
            #pragma unroll
            for (int mt = 0; mt < 4; mt++)
                #pragma unroll
                for (int nt = 0; nt < 4; nt++)
                    mma_tf32(acc[mt][nt], af[mt], bf[nt]);
        }
        __syncthreads();
    }

    #pragma unroll
    for (int mt = 0; mt < 4; mt++) {
        #pragma unroll
        for (int nt = 0; nt < 4; nt++) {
            int r = row0 + wm + mt * 16 + g;
            int c = col0 + wn + nt * 8 + 2 * t4;
            if (r < M)
                *(float2*)&C[(size_t)r * 768 + c] = make_float2(acc[mt][nt][0], acc[mt][nt][1]);
            if (r + 8 < M)
                *(float2*)&C[(size_t)(r + 8) * 768 + c] = make_float2(acc[mt][nt][2], acc[mt][nt][3]);
        }
    }
}

// ---------------- normalize embedding rows -> tf32 buffer --------------------
__global__ void rnorm_kernel(const float* __restrict__ emb) {
    int b = blockIdx.y, i = blockIdx.x;
    const float* row = emb + (size_t)(b * SEQ + 1 + i) * DM;
    float x[3], s = 0.f;
    #pragma unroll
    for (int t = 0; t < 3; t++) {
        x[t] = row[threadIdx.x + t * 256];
        s += x[t] * x[t];
    }
    __shared__ float red[8];
    #pragma unroll
    for (int o = 16; o; o >>= 1) s += __shfl_xor_sync(0xffffffffu, s, o);
    if ((threadIdx.x & 31) == 0) red[threadIdx.x >> 5] = s;
    __syncthreads();
    __shared__ float srn;
    if (threadIdx.x < 8) {
        float v = red[threadIdx.x];
        #pragma unroll
        for (int o = 4; o; o >>= 1) v += __shfl_xor_sync(0xffu, v, o);
        if (threadIdx.x == 0) srn = rsqrtf(v + 1e-12f);
    }
    __syncthreads();
    float rn = srn;
    float* dst = g_En + (size_t)(b * NP + i) * DM;
    #pragma unroll
    for (int t = 0; t < 3; t++)
        dst[threadIdx.x + t * 256] = f2tff(x[t] * rn);
}

// ---------------- penalty = (En . En^T) * dist, via tf32 MMA -----------------
// Per batch: C[576,576] = En[576,768] @ En^T. Block 128x128x32.
__global__ __launch_bounds__(256, 2)
void penalty_mma(const float* __restrict__ pos) {
    __shared__ float Es[128][36];
    __shared__ float Fs[128][36];
    const int b = blockIdx.z;
    const int tid = threadIdx.x;
    const int wid = tid >> 5, lane = tid & 31;
    const int g = lane >> 2, t4 = lane & 3;
    const int wm = (wid >> 2) * 64, wn = (wid & 3) * 32;
    const int i0 = blockIdx.y * 128, j0 = blockIdx.x * 128;
    const float* En = g_En + (size_t)b * NP * DM;

    float acc[4][4][4] = {};
    const int lrow = tid >> 1, lcol = (tid & 1) * 16;

    for (int k0 = 0; k0 < 768; k0 += 32) {
        #pragma unroll
        for (int i = 0; i < 4; i++) {
            int ir = i0 + lrow;
            float4 v = (ir < NP) ? *(const float4*)&En[(size_t)ir * 768 + k0 + lcol + i * 4]
                                 : make_float4(0.f, 0.f, 0.f, 0.f);
            *(float4*)&Es[lrow][lcol + i * 4] = v;
            int jr = j0 + lrow;
            float4 w = (jr < NP) ? *(const float4*)&En[(size_t)jr * 768 + k0 + lcol + i * 4]
                                 : make_float4(0.f, 0.f, 0.f, 0.f);
            *(float4*)&Fs[lrow][lcol + i * 4] = w;
        }
        __syncthreads();

        #pragma unroll
        for (int kk = 0; kk < 32; kk += 8) {
            unsigned af[4][4], bf[4][2];
            #pragma unroll
            for (int mt = 0; mt < 4; mt++) {
                int r = wm + mt * 16;
                af[mt][0] = __float_as_uint(Es[r + g][kk + t4]);
                af[mt][1] = __float_as_uint(Es[r + g + 8][kk + t4]);
                af[mt][2] = __float_as_uint(Es[r + g][kk + t4 + 4]);
                af[mt][3] = __float_as_uint(Es[r + g + 8][kk + t4 + 4]);
            }
            #pragma unroll
            for (int nt = 0; nt < 4; nt++) {
                int c = wn + nt * 8;
                bf[nt][0] = __float_as_uint(Fs[c + g][kk + t4]);      // B[k][n] = En[j=n][k]
                bf[nt][1] = __float_as_uint(Fs[c + g][kk + t4 + 4]);
            }
            #pragma unroll
            for (int mt = 0; mt < 4; mt++)
                #pragma unroll
                for (int nt = 0; nt < 4; nt++)
                    mma_tf32(acc[mt][nt], af[mt], bf[nt]);
        }
        __syncthreads();
    }

    #pragma unroll
    for (int mt = 0; mt < 4; mt++) {
        #pragma unroll
        for (int rr = 0; rr < 2; rr++) {
            int i = i0 + wm + mt * 16 + g + rr * 8;
            if (i >= NP) continue;
            float pix = pos[((size_t)b * NP + i) * 2 + 0];
            float piy = pos[((size_t)b * NP + i) * 2 + 1];
            #pragma unroll
            for (int nt = 0; nt < 4; nt++) {
                #pragma unroll
                for (int cc = 0; cc < 2; cc++) {
                    int j = j0 + wn + nt * 8 + 2 * t4 + cc;
                    if (j >= NP) continue;
                    float dx = pix - pos[((size_t)b * NP + j) * 2 + 0];
                    float dy = piy - pos[((size_t)b * NP + j) * 2 + 1];
                    float dist = sqrtf(dx * dx + dy * dy + 1e-12f);
                    g_pen[((size_t)b * NP + i) * NP + j] = acc[mt][nt][rr * 2 + cc] * dist;
                }
            }
        }
    }
}

// ---------------- flash-style attention with penalty bias --------------------
__global__ void attn_kernel() {
    const int BM = 64, BN = 32;
    __shared__ float Qs[BM][68];
    __shared__ float Ks[BN][68];
    __shared__ float Vs[BN][68];
    __shared__ float Ps[BM][BN + 1];

    const int b = blockIdx.z, h = blockIdx.y, i0 = blockIdx.x * BM;
    const int tid = threadIdx.x;
    const int r = tid >> 2, q = tid & 3;

    for (int t = tid; t < BM * 64; t += 256) {
        int rr = t >> 6, d = t & 63;
        int gi = i0 + rr;
        Qs[rr][d] = (gi < SEQ) ? g_Q[(size_t)(b * SEQ + gi) * DM + h * DKH + d] : 0.f;
    }

    float O[16] = {};
    float m = -CUDART_INF_F, l = 0.f;
    const int gi = i0 + r;

    const int NT = (SEQ + BN - 1) / BN;  // 19
    for (int jt = 0; jt < NT; jt++) {
        const int j0 = jt * BN;
        __syncthreads();
        for (int t = tid; t < BN * 64; t += 256) {
            int cc = t >> 6, d = t & 63;
            int gj = j0 + cc;
            float kv = 0.f, vv = 0.f;
            if (gj < SEQ) {
                kv = g_K[(size_t)(b * SEQ + gj) * DM + h * DKH + d];
                vv = g_V[(size_t)(b * SEQ + gj) * DM + h * DKH + d];
            }
            Ks[cc][d] = kv;
            Vs[cc][d] = vv;
        }
        __syncthreads();

        float s[8] = {};
        #pragma unroll
        for (int k = 0; k < 64; k += 4) {
            float4 qv = *(const float4*)&Qs[r][k];
            #pragma unroll
            for (int cc = 0; cc < 8; cc++) {
                float4 kv = *(const float4*)&Ks[q * 8 + cc][k];
                s[cc] += qv.x * kv.x + qv.y * kv.y + qv.z * kv.z + qv.w * kv.w;
            }
        }

        float mloc = -CUDART_INF_F;
        #pragma unroll
        for (int cc = 0; cc < 8; cc++) {
            int gj = j0 + q * 8 + cc;
            float val = s[cc] * 0.125f;
            if (gi >= 1 && gi < SEQ && gj >= 1 && gj < SEQ)
                val -= g_pen[((size_t)b * NP + gi - 1) * NP + (gj - 1)];
            if (gj >= SEQ) val = -CUDART_INF_F;
            s[cc] = val;
            mloc = fmaxf(mloc, val);
        }
        mloc = fmaxf(mloc, __shfl_xor_sync(0xffffffffu, mloc, 1));
        mloc = fmaxf(mloc, __shfl_xor_sync(0xffffffffu, mloc, 2));
        float mnew = fmaxf(m, mloc);
        float scale = __expf(m - mnew);

        float ssum = 0.f;
        #pragma unroll
        for (int cc = 0; cc < 8; cc++) {
            float e = __expf(s[cc] - mnew);
            Ps[r][q * 8 + cc] = e;
            ssum += e;
        }
        ssum += __shfl_xor_sync(0xffffffffu, ssum, 1);
        ssum += __shfl_xor_sync(0xffffffffu, ssum, 2);
        l = l * scale + ssum;
        m = mnew;
        #pragma unroll
        for (int dd = 0; dd < 16; dd++) O[dd] *= scale;
        __syncthreads();

        #pragma unroll 4
        for (int c = 0; c < BN; c++) {
            float p = Ps[r][c];
            #pragma unroll
            for (int d4 = 0; d4 < 4; d4++) {
                float4 vv = *(const float4*)&Vs[c][q * 16 + d4 * 4];
                O[d4 * 4 + 0] = fmaf(p, vv.x, O[d4 * 4 + 0]);
                O[d4 * 4 + 1] = fmaf(p, vv.y, O[d4 * 4 + 1]);
                O[d4 * 4 + 2] = fmaf(p, vv.z, O[d4 * 4 + 2]);
                O[d4 * 4 + 3] = fmaf(p, vv.w, O[d4 * 4 + 3]);
            }
        }
    }

    if (gi < SEQ) {
        float inv = 1.f / l;
        #pragma unroll
        for (int dd = 0; dd < 16; dd++)
            g_att[(size_t)(b * SEQ + gi) * DM + h * DKH + q * 16 + dd] = O[dd] * inv;
    }
}

// ---------------- residual add + LayerNorm -----------------------------------
__global__ void ln_kernel(const float* __restrict__ fc, const float* __restrict__ resid,
                          const float* __restrict__ gamma, const float* __restrict__ beta,
                          float* __restrict__ out) {
    const int row = blockIdx.x;
    const float* f = fc + (size_t)row * DM;
    const float* rsd = resid + (size_t)row * DM;
    float x[3], s = 0.f, s2 = 0.f;
    #pragma unroll
    for (int t = 0; t < 3; t++) {
        int c = threadIdx.x + t * 256;
        float v = f[c] + rsd[c];
        x[t] = v; s += v; s2 += v * v;
    }
    __shared__ float r1[8], r2[8];
    #pragma unroll
    for (int o = 16; o; o >>= 1) {
        s  += __shfl_xor_sync(0xffffffffu, s, o);
        s2 += __shfl_xor_sync(0xffffffffu, s2, o);
    }
    if ((threadIdx.x & 31) == 0) { r1[threadIdx.x >> 5] = s; r2[threadIdx.x >> 5] = s2; }
    __syncthreads();
    __shared__ float smu, srstd;
    if (threadIdx.x < 8) {
        float a = r1[threadIdx.x], bsum = r2[threadIdx.x];
        #pragma unroll
        for (int o = 4; o; o >>= 1) {
            a    += __shfl_xor_sync(0xffu, a, o);
            bsum += __shfl_xor_sync(0xffu, bsum, o);
        }
        if (threadIdx.x == 0) {
            float mu = a * (1.f / DM);
            float var = bsum * (1.f / DM) - mu * mu;
            smu = mu;
            srstd = rsqrtf(var + 1e-6f);
        }
    }
    __syncthreads();
    float mu = smu, rstd = srstd;
    #pragma unroll
    for (int t = 0; t < 3; t++) {
        int c = threadIdx.x + t * 256;
        out[(size_t)row * DM + c] = (x[t] - mu) * rstd * gamma[c] + beta[c];
    }
}

// ---------------- launch ------------------------------------------------------
extern "C" void kernel_launch(void* const* d_in, const int* in_sizes, int n_in,
                              void* d_out, int out_size) {
    const float* q     = (const float*)d_in[0];
    const float* k     = (const float*)d_in[1];
    const float* v     = (const float*)d_in[2];
    const float* pos   = (const float*)d_in[3];
    const float* emb   = (const float*)d_in[4];
    const float* w_qs  = (const float*)d_in[5];
    const float* w_ks  = (const float*)d_in[6];
    const float* w_vs  = (const float*)d_in[7];
    const float* w_fc  = (const float*)d_in[8];
    const float* gamma = (const float*)d_in[9];
    const float* beta  = (const float*)d_in[10];
    float* out = (float*)d_out;

    float *Qp, *Kp, *Vp, *att;
    cudaGetSymbolAddress((void**)&Qp,  g_Q);
    cudaGetSymbolAddress((void**)&Kp,  g_K);
    cudaGetSymbolAddress((void**)&Vp,  g_V);
    cudaGetSymbolAddress((void**)&att, g_att);

    const int M = BATCH * SEQ;  // 9232
    dim3 gg(6, (M + 127) / 128);  // 6 x 73
    tgemm_768<<<gg, 256>>>(q, w_qs, Qp, M);
    tgemm_768<<<gg, 256>>>(k, w_ks, Kp, M);
    tgemm_768<<<gg, 256>>>(v, w_vs, Vp, M);

    rnorm_kernel<<<dim3(NP, BATCH), 256>>>(emb);
    penalty_mma<<<dim3(5, 5, BATCH), 256>>>(pos);

    attn_kernel<<<dim3((SEQ + 63) / 64, NH, BATCH), 256>>>();

    tgemm_768<<<gg, 256>>>(att, w_fc, Qp, M);  // reuse g_Q for FC output
    ln_kernel<<<M, 256>>>(Qp, q, gamma, beta, out);
}

// round 3
// speedup vs baseline: 1.3830x; 1.0007x over previous
#include <cuda_runtime.h>
#include <math_constants.h>

#define BATCH 16
#define SEQ   577
#define DM    768
#define NH    12
#define DKH   64
#define NP    576   // SEQ - 1 (patch tokens)

// ---------------- scratch (allocation-free per harness rules) ----------------
__device__ float g_Q[BATCH * SEQ * DM];    // Q projection, later reused for FC output
__device__ float g_K[BATCH * SEQ * DM];
__device__ float g_V[BATCH * SEQ * DM];
__device__ float g_att[BATCH * SEQ * DM];  // attention output (head-merged)
__device__ float g_pen[(size_t)BATCH * NP * NP];
__device__ float g_En[(size_t)BATCH * NP * DM];  // normalized embeddings (tf32)

__device__ __forceinline__ unsigned f2tf(float x) {
    unsigned u;
    asm("cvt.rna.tf32.f32 %0, %1;" : "=r"(u) : "f"(x));
    return u;
}
__device__ __forceinline__ float f2tff(float x) { return __uint_as_float(f2tf(x)); }

__device__ __forceinline__ void mma_tf32(float* d, const unsigned* a, const unsigned* b) {
    asm volatile(
        "mma.sync.aligned.m16n8k8.row.col.f32.tf32.tf32.f32 "
        "{%0,%1,%2,%3},{%4,%5,%6,%7},{%8,%9},{%0,%1,%2,%3};"
        : "+f"(d[0]), "+f"(d[1]), "+f"(d[2]), "+f"(d[3])
        : "r"(a[0]), "r"(a[1]), "r"(a[2]), "r"(a[3]), "r"(b[0]), "r"(b[1]));
}

// ---------------- tf32 tensor-core GEMM: C[M,768] = A[M,768] @ W[768,768] -----
// Block 128x128x32, 256 threads = 8 warps (2m x 4n), warp tile 64x32.
__global__ __launch_bounds__(256, 2)
void tgemm_768(const float* __restrict__ A, const float* __restrict__ W,
               float* __restrict__ C, int M) {
    __shared__ float As[128][36];
    __shared__ float Bs[32][132];
    const int tid = threadIdx.x;
    const int wid = tid >> 5, lane = tid & 31;
    const int g = lane >> 2, t4 = lane & 3;
    const int wm = (wid >> 2) * 64, wn = (wid & 3) * 32;
    const int row0 = blockIdx.y * 128, col0 = blockIdx.x * 128;

    float acc[4][4][4] = {};
    const int arow = tid >> 1, acol = (tid & 1) * 16;
    const int brow = tid >> 3, bcol = (tid & 7) * 16;

    for (int k0 = 0; k0 < 768; k0 += 32) {
        const int gr = row0 + arow;
        #pragma unroll
        for (int i = 0; i < 4; i++) {
            float4 v = (gr < M) ? *(const float4*)&A[(size_t)gr * 768 + k0 + acol + i * 4]
                                : make_float4(0.f, 0.f, 0.f, 0.f);
            v.x = f2tff(v.x); v.y = f2tff(v.y); v.z = f2tff(v.z); v.w = f2tff(v.w);
            *(float4*)&As[arow][acol + i * 4] = v;
        }
        #pragma unroll
        for (int i = 0; i < 4; i++) {
            float4 v = *(const float4*)&W[(size_t)(k0 + brow) * 768 + col0 + bcol + i * 4];
            v.x = f2tff(v.x); v.y = f2tff(v.y); v.z = f2tff(v.z); v.w = f2tff(v.w);
            *(float4*)&Bs[brow][bcol + i * 4] = v;
        }
        __syncthreads();

        #pragma unroll
        for (int kk = 0; kk < 32; kk += 8) {
            unsigned af[4][4], bf[4][2];
            #pragma unroll
            for (int mt = 0; mt < 4; mt++) {
                int r = wm + mt * 16;
                af[mt][0] = __float_as_uint(As[r + g][kk + t4]);
                af[mt][1] = __float_as_uint(As[r + g + 8][kk + t4]);
                af[mt][2] = __float_as_uint(As[r + g][kk + t4 + 4]);
                af[mt][3] = __float_as_uint(As[r + g + 8][kk + t4 + 4]);
            }
            #pragma unroll
            for (int nt = 0; nt < 4; nt++) {
                int c = wn + nt * 8;
                bf[nt][0] = __float_as_uint(Bs[kk + t4][c + g]);
                bf[nt][1] = __float_as_uint(Bs[kk + t4 + 4][c + g]);
            }
            #pragma unroll
            for (int mt = 0; mt < 4; mt++)
                #pragma unroll
                for (int nt = 0; nt < 4; nt++)
                    mma_tf32(acc[mt][nt], af[mt], bf[nt]);
        }
        __syncthreads();
    }

    #pragma unroll
    for (int mt = 0; mt < 4; mt++) {
        #pragma unroll
        for (int nt = 0; nt < 4; nt++) {
            int r = row0 + wm + mt * 16 + g;
            int c = col0 + wn + nt * 8 + 2 * t4;
            if (r < M)
                *(float2*)&C[(size_t)r * 768 + c] = make_float2(acc[mt][nt][0], acc[mt][nt][1]);
            if (r + 8 < M)
                *(float2*)&C[(size_t)(r + 8) * 768 + c] = make_float2(acc[mt][nt][2], acc[mt][nt][3]);
        }
    }
}

// ---------------- normalize embedding rows -> tf32 buffer --------------------
__global__ void rnorm_kernel(const float* __restrict__ emb) {
    int b = blockIdx.y, i = blockIdx.x;
    const float* row = emb + (size_t)(b * SEQ + 1 + i) * DM;
    float x[3], s = 0.f;
    #pragma unroll
    for (int t = 0; t < 3; t++) {
        x[t] = row[threadIdx.x + t * 256];
        s += x[t] * x[t];
    }
    __shared__ float red[8];
    #pragma unroll
    for (int o = 16; o; o >>= 1) s += __shfl_xor_sync(0xffffffffu, s, o);
    if ((threadIdx.x & 31) == 0) red[threadIdx.x >> 5] = s;
    __syncthreads();
    __shared__ float srn;
    if (threadIdx.x < 8) {
        float v = red[threadIdx.x];
        #pragma unroll
        for (int o = 4; o; o >>= 1) v += __shfl_xor_sync(0xffu, v, o);
        if (threadIdx.x == 0) srn = rsqrtf(v + 1e-12f);
    }
    __syncthreads();
    float rn = srn;
    float* dst = g_En + (size_t)(b * NP + i) * DM;
    #pragma unroll
    for (int t = 0; t < 3; t++)
        dst[threadIdx.x + t * 256] = f2tff(x[t] * rn);
}

// ---------------- penalty = (En . En^T) * dist, via tf32 MMA -----------------
// Per batch: C[576,576] = En[576,768] @ En^T. Block 128x128x32.
__global__ __launch_bounds__(256, 2)
void penalty_mma(const float* __restrict__ pos) {
    __shared__ float Es[128][36];
    __shared__ float Fs[128][36];
    const int b = blockIdx.z;
    const int tid = threadIdx.x;
    const int wid = tid >> 5, lane = tid & 31;
    const int g = lane >> 2, t4 = lane & 3;
    const int wm = (wid >> 2) * 64, wn = (wid & 3) * 32;
    const int i0 = blockIdx.y * 128, j0 = blockIdx.x * 128;
    const float* En = g_En + (size_t)b * NP * DM;

    float acc[4][4][4] = {};
    const int lrow = tid >> 1, lcol = (tid & 1) * 16;

    for (int k0 = 0; k0 < 768; k0 += 32) {
        #pragma unroll
        for (int i = 0; i < 4; i++) {
            int ir = i0 + lrow;
            float4 v = (ir < NP) ? *(const float4*)&En[(size_t)ir * 768 + k0 + lcol + i * 4]
                                 : make_float4(0.f, 0.f, 0.f, 0.f);
            *(float4*)&Es[lrow][lcol + i * 4] = v;
            int jr = j0 + lrow;
            float4 w = (jr < NP) ? *(const float4*)&En[(size_t)jr * 768 + k0 + lcol + i * 4]
                                 : make_float4(0.f, 0.f, 0.f, 0.f);
            *(float4*)&Fs[lrow][lcol + i * 4] = w;
        }
        __syncthreads();

        #pragma unroll
        for (int kk = 0; kk < 32; kk += 8) {
            unsigned af[4][4], bf[4][2];
            #pragma unroll
            for (int mt = 0; mt < 4; mt++) {
                int r = wm + mt * 16;
                af[mt][0] = __float_as_uint(Es[r + g][kk + t4]);
                af[mt][1] = __float_as_uint(Es[r + g + 8][kk + t4]);
                af[mt][2] = __float_as_uint(Es[r + g][kk + t4 + 4]);
                af[mt][3] = __float_as_uint(Es[r + g + 8][kk + t4 + 4]);
            }
            #pragma unroll
            for (int nt = 0; nt < 4; nt++) {
                int c = wn + nt * 8;
                bf[nt][0] = __float_as_uint(Fs[c + g][kk + t4]);      // B[k][n] = En[j=n][k]
                bf[nt][1] = __float_as_uint(Fs[c + g][kk + t4 + 4]);
            }
            #pragma unroll
            for (int mt = 0; mt < 4; mt++)
                #pragma unroll
                for (int nt = 0; nt < 4; nt++)
                    mma_tf32(acc[mt][nt], af[mt], bf[nt]);
        }
        __syncthreads();
    }

    #pragma unroll
    for (int mt = 0; mt < 4; mt++) {
        #pragma unroll
        for (int rr = 0; rr < 2; rr++) {
            int i = i0 + wm + mt * 16 + g + rr * 8;
            if (i >= NP) continue;
            float pix = pos[((size_t)b * NP + i) * 2 + 0];
            float piy = pos[((size_t)b * NP + i) * 2 + 1];
            #pragma unroll
            for (int nt = 0; nt < 4; nt++) {
                #pragma unroll
                for (int cc = 0; cc < 2; cc++) {
                    int j = j0 + wn + nt * 8 + 2 * t4 + cc;
                    if (j >= NP) continue;
                    float dx = pix - pos[((size_t)b * NP + j) * 2 + 0];
                    float dy = piy - pos[((size_t)b * NP + j) * 2 + 1];
                    float dist = sqrtf(dx * dx + dy * dy + 1e-12f);
                    g_pen[((size_t)b * NP + i) * NP + j] = acc[mt][nt][rr * 2 + cc] * dist;
                }
            }
        }
    }
}

// ---------------- flash-style attention with penalty bias --------------------
__global__ void attn_kernel() {
    const int BM = 64, BN = 32;
    __shared__ float Qs[BM][68];
    __shared__ float Ks[BN][68];
    __shared__ float Vs[BN][68];
    __shared__ float Ps[BM][BN + 1];

    const int b = blockIdx.z, h = blockIdx.y, i0 = blockIdx.x * BM;
    const int tid = threadIdx.x;
    const int r = tid >> 2, q = tid & 3;

    for (int t = tid; t < BM * 64; t += 256) {
        int rr = t >> 6, d = t & 63;
        int gi = i0 + rr;
        Qs[rr][d] = (gi < SEQ) ? g_Q[(size_t)(b * SEQ + gi) * DM + h * DKH + d] : 0.f;
    }

    float O[16] = {};
    float m = -CUDART_INF_F, l = 0.f;
    const int gi = i0 + r;

    const int NT = (SEQ + BN - 1) / BN;  // 19
    for (int jt = 0; jt < NT; jt++) {
        const int j0 = jt * BN;
        __syncthreads();
        for (int t = tid; t < BN * 64; t += 256) {
            int cc = t >> 6, d = t & 63;
            int gj = j0 + cc;
            float kv = 0.f, vv = 0.f;
            if (gj < SEQ) {
                kv = g_K[(size_t)(b * SEQ + gj) * DM + h * DKH + d];
                vv = g_V[(size_t)(b * SEQ + gj) * DM + h * DKH + d];
            }
            Ks[cc][d] = kv;
            Vs[cc][d] = vv;
        }
        __syncthreads();

        float s[8] = {};
        #pragma unroll
        for (int k = 0; k < 64; k += 4) {
            float4 qv = *(const float4*)&Qs[r][k];
            #pragma unroll
            for (int cc = 0; cc < 8; cc++) {
                float4 kv = *(const float4*)&Ks[q * 8 + cc][k];
                s[cc] += qv.x * kv.x + qv.y * kv.y + qv.z * kv.z + qv.w * kv.w;
            }
        }

        float mloc = -CUDART_INF_F;
        #pragma unroll
        for (int cc = 0; cc < 8; cc++) {
            int gj = j0 + q * 8 + cc;
            float val = s[cc] * 0.125f;
            if (gi >= 1 && gi < SEQ && gj >= 1 && gj < SEQ)
                val -= g_pen[((size_t)b * NP + gi - 1) * NP + (gj - 1)];
            if (gj >= SEQ) val = -CUDART_INF_F;
            s[cc] = val;
            mloc = fmaxf(mloc, val);
        }
        mloc = fmaxf(mloc, __shfl_xor_sync(0xffffffffu, mloc, 1));
        mloc = fmaxf(mloc, __shfl_xor_sync(0xffffffffu, mloc, 2));
        float mnew = fmaxf(m, mloc);
        float scale = __expf(m - mnew);

        float ssum = 0.f;
        #pragma unroll
        for (int cc = 0; cc < 8; cc++) {
            float e = __expf(s[cc] - mnew);
            Ps[r][q * 8 + cc] = e;
            ssum += e;
        }
        ssum += __shfl_xor_sync(0xffffffffu, ssum, 1);
        ssum += __shfl_xor_sync(0xffffffffu, ssum, 2);
        l = l * scale + ssum;
        m = mnew;
        #pragma unroll
        for (int dd = 0; dd < 16; dd++) O[dd] *= scale;
        __syncthreads();

        #pragma unroll 4
        for (int c = 0; c < BN; c++) {
            float p = Ps[r][c];
            #pragma unroll
            for (int d4 = 0; d4 < 4; d4++) {
                float4 vv = *(const float4*)&Vs[c][q * 16 + d4 * 4];
                O[d4 * 4 + 0] = fmaf(p, vv.x, O[d4 * 4 + 0]);
                O[d4 * 4 + 1] = fmaf(p, vv.y, O[d4 * 4 + 1]);
                O[d4 * 4 + 2] = fmaf(p, vv.z, O[d4 * 4 + 2]);
                O[d4 * 4 + 3] = fmaf(p, vv.w, O[d4 * 4 + 3]);
            }
        }
    }

    if (gi < SEQ) {
        float inv = 1.f / l;
        #pragma unroll
        for (int dd = 0; dd < 16; dd++)
            g_att[(size_t)(b * SEQ + gi) * DM + h * DKH + q * 16 + dd] = O[dd] * inv;
    }
}

// ---------------- residual add + LayerNorm -----------------------------------
__global__ void ln_kernel(const float* __restrict__ fc, const float* __restrict__ resid,
                          const float* __restrict__ gamma, const float* __restrict__ beta,
                          float* __restrict__ out) {
    const int row = blockIdx.x;
    const float* f = fc + (size_t)row * DM;
    const float* rsd = resid + (size_t)row * DM;
    float x[3], s = 0.f, s2 = 0.f;
    #pragma unroll
    for (int t = 0; t < 3; t++) {
        int c = threadIdx.x + t * 256;
        float v = f[c] + rsd[c];
        x[t] = v; s += v; s2 += v * v;
    }
    __shared__ float r1[8], r2[8];
    #pragma unroll
    for (int o = 16; o; o >>= 1) {
        s  += __shfl_xor_sync(0xffffffffu, s, o);
        s2 += __shfl_xor_sync(0xffffffffu, s2, o);
    }
    if ((threadIdx.x & 31) == 0) { r1[threadIdx.x >> 5] = s; r2[threadIdx.x >> 5] = s2; }
    __syncthreads();
    __shared__ float smu, srstd;
    if (threadIdx.x < 8) {
        float a = r1[threadIdx.x], bsum = r2[threadIdx.x];
        #pragma unroll
        for (int o = 4; o; o >>= 1) {
            a    += __shfl_xor_sync(0xffu, a, o);
            bsum += __shfl_xor_sync(0xffu, bsum, o);
        }
        if (threadIdx.x == 0) {
            float mu = a * (1.f / DM);
            float var = bsum * (1.f / DM) - mu * mu;
            smu = mu;
            srstd = rsqrtf(var + 1e-6f);
        }
    }
    __syncthreads();
    float mu = smu, rstd = srstd;
    #pragma unroll
    for (int t = 0; t < 3; t++) {
        int c = threadIdx.x + t * 256;
        out[(size_t)row * DM + c] = (x[t] - mu) * rstd * gamma[c] + beta[c];
    }
}

// ---------------- launch ------------------------------------------------------
extern "C" void kernel_launch(void* const* d_in, const int* in_sizes, int n_in,
                              void* d_out, int out_size) {
    const float* q     = (const float*)d_in[0];
    const float* k     = (const float*)d_in[1];
    const float* v     = (const float*)d_in[2];
    const float* pos   = (const float*)d_in[3];
    const float* emb   = (const float*)d_in[4];
    const float* w_qs  = (const float*)d_in[5];
    const float* w_ks  = (const float*)d_in[6];
    const float* w_vs  = (const float*)d_in[7];
    const float* w_fc  = (const float*)d_in[8];
    const float* gamma = (const float*)d_in[9];
    const float* beta  = (const float*)d_in[10];
    float* out = (float*)d_out;

    float *Qp, *Kp, *Vp, *att;
    cudaGetSymbolAddress((void**)&Qp,  g_Q);
    cudaGetSymbolAddress((void**)&Kp,  g_K);
    cudaGetSymbolAddress((void**)&Vp,  g_V);
    cudaGetSymbolAddress((void**)&att, g_att);

    const int M = BATCH * SEQ;  // 9232
    dim3 gg(6, (M + 127) / 128);  // 6 x 73
    tgemm_768<<<gg, 256>>>(q, w_qs, Qp, M);
    tgemm_768<<<gg, 256>>>(k, w_ks, Kp, M);
    tgemm_768<<<gg, 256>>>(v, w_vs, Vp, M);

    rnorm_kernel<<<dim3(NP, BATCH), 256>>>(emb);
    penalty_mma<<<dim3(5, 5, BATCH), 256>>>(pos);

    attn_kernel<<<dim3((SEQ + 63) / 64, NH, BATCH), 256>>>();

    tgemm_768<<<gg, 256>>>(att, w_fc, Qp, M);  // reuse g_Q for FC output
    ln_kernel<<<M, 256>>>(Qp, q, gamma, beta, out);
}